// round 16
// baseline (speedup 1.0000x reference)
#include <cuda_runtime.h>
#include <cuda_fp16.h>
#include <math.h>
#include <stdint.h>

// Problem constants
#define NTOK (8*8192)        // 65536 tokens
#define DIMC 512
#define NSLOT 64
#define CHUNKT 64
#define NCHUNK (NTOK/CHUNKT) // 1024

// ---------------- scratch ----------------
__device__ __half g_x16  [(size_t)NTOK*DIMC];
__device__ __half g_v16  [(size_t)NTOK*DIMC];
__device__ __half g_ret16[(size_t)NTOK*DIMC];
__device__ __half g_ww [(size_t)NTOK*NSLOT];
__device__ __half g_rw [(size_t)NTOK*NSLOT];
__device__ __half g_WvT16[DIMC*DIMC];   // half(Wv) transposed: [n][k]
__device__ __half g_WoT16[DIMC*DIMC];   // half(ln_g ⊙ Wo) transposed: [n][k]
__device__ __half g_P16T [128*DIMC];    // half([Wk@SKᵀ | Wq@SKᵀ]) transposed: [s][k]
__device__ float  g_c   [128];
__device__ float  g_b2  [DIMC];         // bo + ln_b @ Wo
__device__ float  g_cs  [DIMC];         // colsum of (ln_g ⊙ Wo)
__device__ float  g_mu  [NTOK];
__device__ float  g_ri  [NTOK];

// ---------------- helpers ----------------
__device__ __forceinline__ unsigned f2tf32(float x) {
    unsigned r;
    asm("cvt.rna.tf32.f32 %0, %1;" : "=r"(r) : "f"(x));
    return r;
}

__device__ __forceinline__ void mma_tf32(float c[4],
    unsigned a0, unsigned a1, unsigned a2, unsigned a3,
    unsigned b0, unsigned b1)
{
    asm volatile(
        "mma.sync.aligned.m16n8k8.row.col.f32.tf32.tf32.f32 "
        "{%0,%1,%2,%3},{%4,%5,%6,%7},{%8,%9},{%0,%1,%2,%3};"
        : "+f"(c[0]), "+f"(c[1]), "+f"(c[2]), "+f"(c[3])
        : "r"(a0), "r"(a1), "r"(a2), "r"(a3), "r"(b0), "r"(b1));
}

__device__ __forceinline__ void mma_f16(float c[4],
    unsigned a0, unsigned a1, unsigned a2, unsigned a3,
    unsigned b0, unsigned b1)
{
    asm volatile(
        "mma.sync.aligned.m16n8k16.row.col.f32.f16.f16.f32 "
        "{%0,%1,%2,%3},{%4,%5,%6,%7},{%8,%9},{%0,%1,%2,%3};"
        : "+f"(c[0]), "+f"(c[1]), "+f"(c[2]), "+f"(c[3])
        : "r"(a0), "r"(a1), "r"(a2), "r"(a3), "r"(b0), "r"(b1));
}

__device__ __forceinline__ void ldsm_x4(
    unsigned& r0, unsigned& r1, unsigned& r2, unsigned& r3, unsigned addr)
{
    asm volatile("ldmatrix.sync.aligned.m8n8.x4.shared.b16 {%0,%1,%2,%3}, [%4];"
        : "=r"(r0), "=r"(r1), "=r"(r2), "=r"(r3) : "r"(addr));
}

__device__ __forceinline__ void cpcg16(unsigned smem_addr, const void* g) {
    asm volatile("cp.async.cg.shared.global [%0], [%1], 16;\n"
                 :: "r"(smem_addr), "l"(g));
}
#define CP_COMMIT() asm volatile("cp.async.commit_group;\n" ::: "memory")
#define CP_WAIT0()  asm volatile("cp.async.wait_group 0;\n" ::: "memory")
#define CP_WAIT1()  asm volatile("cp.async.wait_group 1;\n" ::: "memory")

// ======== fused prep + x->half (overlapped in one launch) ========
#define N2H 16384

__global__ __launch_bounds__(256) void prep_fused(
    const float* __restrict__ Wk, const float* __restrict__ bk,
    const float* __restrict__ Wq, const float* __restrict__ bq,
    const float* __restrict__ SK,
    const float* __restrict__ Wv, const float* __restrict__ Wo,
    const float* __restrict__ lng, const float* __restrict__ lnb,
    const float* __restrict__ bo,
    __half* __restrict__ P16T, float* __restrict__ c,
    __half* __restrict__ WvT16, __half* __restrict__ WoT16,
    float* __restrict__ b2, float* __restrict__ cs,
    const float* __restrict__ X, __half* __restrict__ X16)
{
    const int blk = blockIdx.x;
    const int s = threadIdx.x;

    if (blk >= 514) {
        size_t base = ((size_t)(blk - 514) * 256 + s) * 8;
        float4 a = *(const float4*)(X + base);
        float4 b = *(const float4*)(X + base + 4);
        __half2 h[4];
        h[0] = __floats2half2_rn(a.x, a.y);
        h[1] = __floats2half2_rn(a.z, a.w);
        h[2] = __floats2half2_rn(b.x, b.y);
        h[3] = __floats2half2_rn(b.z, b.w);
        *(uint4*)(X16 + base) = *(uint4*)h;
        return;
    }

    if (blk == 513) {
        #pragma unroll
        for (int j = 0; j < 2; j++) {
            int n = s * 2 + j;
            float a = 0.f, g = 0.f;
            for (int k = 0; k < DIMC; k++) {
                float w = Wo[(size_t)k*DIMC + n];
                a = fmaf(lnb[k], w, a);
                g = fmaf(lng[k], w, g);
            }
            b2[n] = a + bo[n];
            cs[n] = g;
        }
        return;
    }

    __shared__ float rk[DIMC];
    __shared__ float rq[DIMC];
    if (blk < DIMC) {
        for (int d = s; d < DIMC; d += 256) {
            rk[d] = Wk[(size_t)blk*DIMC + d];
            rq[d] = Wq[(size_t)blk*DIMC + d];
        }
    } else {
        for (int d = s; d < DIMC; d += 256) { rk[d] = bk[d]; rq[d] = bq[d]; }
    }
    __syncthreads();

    if (s < 128) {
        const int slot = s & 63;
        const float* row = (s < 64) ? rk : rq;
        float a = 0.f;
        const float* skr = SK + (size_t)slot*DIMC;
        #pragma unroll 8
        for (int d = 0; d < DIMC; d++) a = fmaf(row[d], skr[d], a);
        if (blk < DIMC) P16T[(size_t)s*DIMC + blk] = __float2half_rn(a);
        else            c[s] = a;
    }
    if (blk < DIMC) {
        const float gk = lng[blk];
        for (int n = s; n < DIMC; n += 256) {
            WvT16[(size_t)n*DIMC + blk] = __float2half_rn(Wv[(size_t)blk*DIMC + n]);
            WoT16[(size_t)n*DIMC + blk] = __float2half_rn(gk * Wo[(size_t)blk*DIMC + n]);
        }
    }
}

// ======== fp16 GEMM, ldmatrix, 4-stage cp.async, 2-chunk rounds ========
#define HROWB 80
#define HSTG 10240
#define HSMEM (8*HSTG)      // 81920
#define NRND 8              // 8 rounds x 64-K

__global__ __launch_bounds__(256, 2) void gemm_h(
    const __half* __restrict__ A16, const __half* __restrict__ BT16,
    const float* __restrict__ bias, const float* __restrict__ resid,
    float* __restrict__ C, __half* __restrict__ C16,
    const float* __restrict__ rowmu, const float* __restrict__ rowri,
    const float* __restrict__ cs,
    const __half* __restrict__ P16T, const float* __restrict__ cvec,
    const float* __restrict__ scale_p,
    __half* __restrict__ ww, __half* __restrict__ rw, int nNormal)
{
    extern __shared__ __align__(16) char smraw[];
    float* L = (float*)smraw;          // logits alias [128][68]
    __shared__ float csh[128];

    const int tid  = threadIdx.x;
    const int lane = tid & 31;
    const int wid  = tid >> 5;
    const int warp_m = wid >> 2;
    const int warp_n = wid & 3;
    const int gid = lane >> 2;
    const int tig = lane & 3;
    const int m0 = blockIdx.y * 128;
    const bool is_logit = (P16T != nullptr) && ((int)blockIdx.x == nNormal);
    const int n0 = is_logit ? 0 : blockIdx.x * 128;
    const __half* Bsrc = is_logit ? P16T : BT16;

    if (is_logit && tid < 128) csh[tid] = cvec[tid];

    const unsigned sb = (unsigned)__cvta_generic_to_shared(smraw);

    const int grp = lane >> 3;
    const unsigned aRowL = (unsigned)(warp_m*64 + (grp & 1)*8 + (lane & 7));
    const unsigned aKadd = (unsigned)((grp >> 1) * 16);
    const unsigned bRowL = (unsigned)(warp_n*32 + (grp >> 1)*8 + (lane & 7));
    const unsigned bKadd = (unsigned)((grp & 1) * 16);

    float acc[4][4][4] = {};

    auto stageAB = [&](int st, int k0) {
        #pragma unroll
        for (int h = 0; h < 2; h++) {
            int cch = tid + h*256;
            int r = cch >> 2, j = cch & 3;
            unsigned off = (unsigned)(r*HROWB + j*16);
            cpcg16(sb + st*HSTG + off, A16 + (size_t)(m0 + r)*DIMC + k0 + j*8);
            cpcg16(sb + 4*HSTG + st*HSTG + off, Bsrc + (size_t)(n0 + r)*DIMC + k0 + j*8);
        }
    };

    // prologue: two 2-chunk groups (chunks 0..3 -> stages 0..3)
    stageAB(0, 0);   stageAB(1, 32);  CP_COMMIT();
    stageAB(2, 64);  stageAB(3, 96);  CP_COMMIT();

    for (int r = 0; r < NRND; r++) {
        if (r == NRND - 1) { CP_WAIT0(); } else { CP_WAIT1(); }
        __syncthreads();

        // compute chunks 2r, 2r+1 (stages (2r)&3, (2r+1)&3): 64 HMMA run
        #pragma unroll
        for (int cc = 0; cc < 2; cc++) {
            const int st = (2*r + cc) & 3;
            const unsigned aB = sb + st*HSTG + aRowL*HROWB + aKadd;
            const unsigned bB = sb + 4*HSTG + st*HSTG + bRowL*HROWB + bKadd;
            #pragma unroll
            for (int ks = 0; ks < 2; ks++) {
                unsigned af[4][4];
                #pragma unroll
                for (int mt = 0; mt < 4; mt++)
                    ldsm_x4(af[mt][0], af[mt][1], af[mt][2], af[mt][3],
                            aB + (unsigned)(mt*16*HROWB + ks*32));
                unsigned bf[4][2];
                #pragma unroll
                for (int ntp = 0; ntp < 2; ntp++)
                    ldsm_x4(bf[2*ntp][0], bf[2*ntp][1], bf[2*ntp+1][0], bf[2*ntp+1][1],
                            bB + (unsigned)(ntp*16*HROWB + ks*32));
                #pragma unroll
                for (int mt = 0; mt < 4; mt++)
                    #pragma unroll
                    for (int nt = 0; nt < 4; nt++)
                        mma_f16(acc[mt][nt], af[mt][0], af[mt][1], af[mt][2], af[mt][3],
                                bf[nt][0], bf[nt][1]);
            }
        }

        // stage chunks 2r+4, 2r+5 into the stages just consumed
        if (r < NRND - 2) {
            __syncthreads();
            stageAB((2*r) & 3,     (2*r + 4) * 32);
            stageAB((2*r + 1) & 3, (2*r + 5) * 32);
            CP_COMMIT();
        }
    }

    if (!is_logit) {
        #pragma unroll
        for (int nt = 0; nt < 4; nt++) {
            int cb = n0 + warp_n * 32 + nt * 8 + 2 * tig;
            float b0 = bias[cb], b1 = bias[cb + 1];
            float cs0 = 0.f, cs1 = 0.f;
            if (rowmu) { cs0 = cs[cb]; cs1 = cs[cb + 1]; }
            #pragma unroll
            for (int mt = 0; mt < 4; mt++) {
                int rA = m0 + warp_m * 64 + mt * 16 + gid;
                int rB = rA + 8;
                size_t offA = (size_t)rA * DIMC + cb;
                size_t offB = (size_t)rB * DIMC + cb;
                if (rowmu) {
                    float muA = rowmu[rA], riA = rowri[rA];
                    float muB = rowmu[rB], riB = rowri[rB];
                    float2 o0, o1;
                    o0.x = riA*acc[mt][nt][0] - riA*muA*cs0 + b0;
                    o0.y = riA*acc[mt][nt][1] - riA*muA*cs1 + b1;
                    o1.x = riB*acc[mt][nt][2] - riB*muB*cs0 + b0;
                    o1.y = riB*acc[mt][nt][3] - riB*muB*cs1 + b1;
                    float2 e0 = *(const float2*)(resid + offA);
                    float2 e1 = *(const float2*)(resid + offB);
                    o0.x += e0.x; o0.y += e0.y;
                    o1.x += e1.x; o1.y += e1.y;
                    *(float2*)(C + offA) = o0;
                    *(float2*)(C + offB) = o1;
                } else {
                    *(__half2*)(C16 + offA) =
                        __floats2half2_rn(acc[mt][nt][0] + b0, acc[mt][nt][1] + b1);
                    *(__half2*)(C16 + offB) =
                        __floats2half2_rn(acc[mt][nt][2] + b0, acc[mt][nt][3] + b1);
                }
            }
        }
    } else {
        __syncthreads();
        const float sc = scale_p[0];
        #pragma unroll
        for (int pass = 0; pass < 2; pass++) {
            if ((warp_n >> 1) == pass) {
                int halfn = warp_n & 1;
                #pragma unroll
                for (int nt = 0; nt < 4; nt++) {
                    int cl = halfn * 32 + nt * 8 + 2 * tig;
                    int cg = pass * 64 + cl;
                    float c0v = csh[cg], c1v = csh[cg + 1];
                    #pragma unroll
                    for (int mt = 0; mt < 4; mt++) {
                        int rr = warp_m * 64 + mt * 16 + gid;
                        L[ rr    *68 + cl    ] = (acc[mt][nt][0] + c0v) * sc;
                        L[ rr    *68 + cl + 1] = (acc[mt][nt][1] + c1v) * sc;
                        L[(rr+8) *68 + cl    ] = (acc[mt][nt][2] + c0v) * sc;
                        L[(rr+8) *68 + cl + 1] = (acc[mt][nt][3] + c1v) * sc;
                    }
                }
            }
            __syncthreads();
            {
                int t = tid >> 1, hh = tid & 1;
                float* Lr = L + t*68 + hh*32;
                float mx = -1e30f;
                #pragma unroll 8
                for (int s = 0; s < 32; s++) mx = fmaxf(mx, Lr[s]);
                mx = fmaxf(mx, __shfl_xor_sync(0xffffffffu, mx, 1));
                float sum = 0.f;
                #pragma unroll 8
                for (int s = 0; s < 32; s++) { float e = expf(Lr[s]-mx); Lr[s] = e; sum += e; }
                sum += __shfl_xor_sync(0xffffffffu, sum, 1);
                float rv = 1.f / sum;
                __half* op = (pass ? rw : ww) + (size_t)(m0 + t) * NSLOT + hh*32;
                #pragma unroll
                for (int s = 0; s < 32; s += 4) {
                    __half2 p0 = __floats2half2_rn(Lr[s]*rv,   Lr[s+1]*rv);
                    __half2 p1 = __floats2half2_rn(Lr[s+2]*rv, Lr[s+3]*rv);
                    uint2 u;
                    u.x = *(unsigned*)&p0;
                    u.y = *(unsigned*)&p1;
                    *(uint2*)(op + s) = u;
                }
            }
            __syncthreads();
        }
    }
}

// ======== per-chunk tf32 MMA + fused LN stats + reg-staged V prefetch ========
#define CSMEM (64*68*4*2 + 64*132*4)   // 68608

__global__ __launch_bounds__(256) void chunk_attn_mma(
    const __half* __restrict__ rwh, const __half* __restrict__ wwh,
    const __half* __restrict__ v16, __half* __restrict__ ret16,
    float* __restrict__ mu, float* __restrict__ ri)
{
    extern __shared__ __align__(16) char cbuf[];
    unsigned* RW = (unsigned*)cbuf;
    unsigned* WT = RW + 64*68;
    unsigned* VS = WT + 64*68;
    float*    red = (float*)VS;        // 512 floats, used after last slice
    const int tid  = threadIdx.x;
    const int lane = tid & 31;
    const int wid  = tid >> 5;
    const int gid = lane >> 2;
    const int tig = lane & 3;
    const int chunk0 = blockIdx.x * CHUNKT;

    int vr[4], vc[4];
    #pragma unroll
    for (int k = 0; k < 4; k++) {
        int idx = tid + k*256;
        vr[k] = idx >> 4;
        vc[k] = (idx & 15) << 3;
    }

    uint4 pv[4];
    #pragma unroll
    for (int k = 0; k < 4; k++)
        pv[k] = *(const uint4*)(v16 + (size_t)(chunk0+vr[k])*DIMC + vc[k]);

    #pragma unroll
    for (int k = 0; k < 4; k++) {
        int idx = tid + k*256;
        int r = idx >> 4, c4 = (idx & 15) << 2;
        uint2 ha = *(const uint2*)(rwh + (size_t)(chunk0+r)*NSLOT + c4);
        float2 a0 = __half22float2(*(__half2*)&ha.x);
        float2 a1 = __half22float2(*(__half2*)&ha.y);
        float4 va; va.x = a0.x; va.y = a0.y; va.z = a1.x; va.w = a1.y;
        *(float4*)(RW + r*68 + c4) = va;
        uint2 hb = *(const uint2*)(wwh + (size_t)(chunk0+r)*NSLOT + c4);
        float2 b0 = __half22float2(*(__half2*)&hb.x);
        float2 b1 = __half22float2(*(__half2*)&hb.y);
        WT[(c4    )*68 + r] = __float_as_uint(b0.x);
        WT[(c4 + 1)*68 + r] = __float_as_uint(b0.y);
        WT[(c4 + 2)*68 + r] = __float_as_uint(b1.x);
        WT[(c4 + 3)*68 + r] = __float_as_uint(b1.y);
    }
    __syncthreads();

    const int wm = wid >> 2;
    const int wn = wid & 3;
    float a1acc[2][2][4] = {};
    #pragma unroll
    for (int kk = 0; kk < 64; kk += 8) {
        unsigned af[2][4];
        #pragma unroll
        for (int mt = 0; mt < 2; mt++) {
            int r = wm*32 + mt*16 + gid;
            af[mt][0] = RW[ r     *68 + kk + tig    ];
            af[mt][1] = RW[(r + 8)*68 + kk + tig    ];
            af[mt][2] = RW[ r     *68 + kk + tig + 4];
            af[mt][3] = RW[(r + 8)*68 + kk + tig + 4];
        }
        unsigned bf[2][2];
        #pragma unroll
        for (int nt = 0; nt < 2; nt++) {
            int cc = wn*16 + nt*8 + gid;
            bf[nt][0] = WT[(kk + tig    )*68 + cc];
            bf[nt][1] = WT[(kk + tig + 4)*68 + cc];
        }
        #pragma unroll
        for (int mt = 0; mt < 2; mt++)
            #pragma unroll
            for (int nt = 0; nt < 2; nt++)
                mma_tf32(a1acc[mt][nt], af[mt][0], af[mt][1], af[mt][2], af[mt][3],
                         bf[nt][0], bf[nt][1]);
    }
    __syncthreads();

    #pragma unroll
    for (int mt = 0; mt < 2; mt++) {
        int r0 = wm*32 + mt*16 + gid;
        #pragma unroll
        for (int nt = 0; nt < 2; nt++) {
            int cc = wn*16 + nt*8 + 2*tig;
            RW[ r0    *68 + cc    ] = f2tf32((cc     <= r0    ) ? a1acc[mt][nt][0] : 0.f);
            RW[ r0    *68 + cc + 1] = f2tf32((cc + 1 <= r0    ) ? a1acc[mt][nt][1] : 0.f);
            RW[(r0+8) *68 + cc    ] = f2tf32((cc     <= r0 + 8) ? a1acc[mt][nt][2] : 0.f);
            RW[(r0+8) *68 + cc + 1] = f2tf32((cc + 1 <= r0 + 8) ? a1acc[mt][nt][3] : 0.f);
        }
    }
    __syncthreads();

    float s_acc[2][2] = {}, ss_acc[2][2] = {};

    for (int d0 = 0; d0 < DIMC; d0 += 128) {
        #pragma unroll
        for (int k = 0; k < 4; k++) {
            float2 f0 = __half22float2(*(__half2*)&pv[k].x);
            float2 f1 = __half22float2(*(__half2*)&pv[k].y);
            float2 f2 = __half22float2(*(__half2*)&pv[k].z);
            float2 f3 = __half22float2(*(__half2*)&pv[k].w);
            float4 o0; o0.x = f0.x; o0.y = f0.y; o0.z = f1.x; o0.w = f1.y;
            float4 o1; o1.x = f2.x; o1.y = f2.y; o1.z = f3.x; o1.w = f3.y;
            *(float4*)(VS + vr[k]*132 + vc[k])     = o0;
            *(float4*)(VS + vr[k]*132 + vc[k] + 4) = o1;
        }
        __syncthreads();

        if (d0 + 128 < DIMC) {
            #pragma unroll
            for (int k = 0; k < 4; k++)
                pv[k] = *(const uint4*)(v16 + (size_t)(chunk0+vr[k])*DIMC
                                        + d0 + 128 + vc[k]);
        }

        float a2[2][4][4] = {};
        #pragma unroll
        for (int ks = 0; ks < 8; ks++) {
            unsigned af[2][4];
            #pragma unroll
            for (int mt = 0; mt < 2; mt++) {
                int r = wm*32 + mt*16 + gid;
                af[mt][0] = RW[ r     *68 + ks*8 + tig    ];
                af[mt][1] = RW[(r + 8)*68 + ks*8 + tig    ];
                af[mt][2] = RW[ r     *68 + ks*8 + tig + 4];
                af[mt][3] = RW[(r + 8)*68 + ks*8 + tig + 4];
            }
            unsigned bf[4][2];
            #pragma unroll
            for (int nt = 0; nt < 4; nt++) {
                int cc = wn*32 + nt*8 + gid;
                bf[nt][0] = VS[(ks*8 + tig    )*132 + cc];
                bf[nt][1] = VS[(ks*8 + tig + 4)*132 + cc];
            }
            #pragma unroll
            for (int mt = 0; mt < 2; mt++)
                #pragma unroll
                for (int nt = 0; nt < 4; nt++)
                    mma_tf32(a2[mt][nt], af[mt][0], af[mt][1],
                             af[mt][2], af[mt][3], bf[nt][0], bf[nt][1]);
        }

        #pragma unroll
        for (int mt = 0; mt < 2; mt++) {
            int r0 = wm*32 + mt*16 + gid;
            #pragma unroll
            for (int nt = 0; nt < 4; nt++) {
                int cc = wn*32 + nt*8 + 2*tig;
                __half2 h0 = __floats2half2_rn(a2[mt][nt][0], a2[mt][nt][1]);
                __half2 h1 = __floats2half2_rn(a2[mt][nt][2], a2[mt][nt][3]);
                *(__half2*)(ret16 + (size_t)(chunk0 + r0    )*DIMC + d0 + cc) = h0;
                *(__half2*)(ret16 + (size_t)(chunk0 + r0 + 8)*DIMC + d0 + cc) = h1;
                float2 f0 = __half22float2(h0);
                float2 f1 = __half22float2(h1);
                s_acc[mt][0]  += f0.x + f0.y;
                ss_acc[mt][0] += fmaf(f0.x, f0.x, f0.y*f0.y);
                s_acc[mt][1]  += f1.x + f1.y;
                ss_acc[mt][1] += fmaf(f1.x, f1.x, f1.y*f1.y);
            }
        }
        __syncthreads();
    }

    #pragma unroll
    for (int mt = 0; mt < 2; mt++)
        #pragma unroll
        for (int hf = 0; hf < 2; hf++) {
            float s = s_acc[mt][hf], ss = ss_acc[mt][hf];
            s  += __shfl_xor_sync(0xffffffffu, s, 1);
            s  += __shfl_xor_sync(0xffffffffu, s, 2);
            ss += __shfl_xor_sync(0xffffffffu, ss, 1);
            ss += __shfl_xor_sync(0xffffffffu, ss, 2);
            if (tig == 0) {
                int row = wm*32 + mt*16 + hf*8 + gid;
                red[wn*64 + row]       = s;
                red[256 + wn*64 + row] = ss;
            }
        }
    __syncthreads();
    if (tid < 64) {
        float s  = red[tid] + red[64+tid] + red[128+tid] + red[192+tid];
        float ss = red[256+tid] + red[320+tid] + red[384+tid] + red[448+tid];
        float m = s * (1.f/512.f);
        mu[chunk0 + tid] = m;
        ri[chunk0 + tid] = rsqrtf(ss * (1.f/512.f) - m*m + 1e-5f);
    }
}

// ---------------- launch ----------------
extern "C" void kernel_launch(void* const* d_in, const int* in_sizes, int n_in,
                              void* d_out, int out_size)
{
    (void)in_sizes; (void)n_in; (void)out_size;
    const float* x   = (const float*)d_in[0];
    const float* sk  = (const float*)d_in[1];
    const float* Wk  = (const float*)d_in[2];
    const float* bk  = (const float*)d_in[3];
    const float* Wq  = (const float*)d_in[4];
    const float* bq  = (const float*)d_in[5];
    const float* Wv  = (const float*)d_in[6];
    const float* bv  = (const float*)d_in[7];
    const float* sc  = (const float*)d_in[8];
    const float* lng = (const float*)d_in[9];
    const float* lnb = (const float*)d_in[10];
    const float* Wo  = (const float*)d_in[11];
    const float* bo  = (const float*)d_in[12];
    float* out = (float*)d_out;

    float *cp,*b2p,*csp,*mup,*rip;
    __half *x16p,*v16p,*ret16p,*WvTp,*WoTp,*P16p,*wwp,*rwp;
    cudaGetSymbolAddress((void**)&x16p,  g_x16);
    cudaGetSymbolAddress((void**)&v16p,  g_v16);
    cudaGetSymbolAddress((void**)&ret16p,g_ret16);
    cudaGetSymbolAddress((void**)&wwp,   g_ww);
    cudaGetSymbolAddress((void**)&rwp,   g_rw);
    cudaGetSymbolAddress((void**)&cp,    g_c);
    cudaGetSymbolAddress((void**)&b2p,   g_b2);
    cudaGetSymbolAddress((void**)&csp,   g_cs);
    cudaGetSymbolAddress((void**)&mup,   g_mu);
    cudaGetSymbolAddress((void**)&rip,   g_ri);
    cudaGetSymbolAddress((void**)&WvTp,  g_WvT16);
    cudaGetSymbolAddress((void**)&WoTp,  g_WoT16);
    cudaGetSymbolAddress((void**)&P16p,  g_P16T);

    cudaFuncSetAttribute(gemm_h, cudaFuncAttributeMaxDynamicSharedMemorySize, HSMEM);
    cudaFuncSetAttribute(chunk_attn_mma, cudaFuncAttributeMaxDynamicSharedMemorySize, CSMEM);

    prep_fused<<<514 + N2H, 256>>>(Wk, bk, Wq, bq, sk, Wv, Wo, lng, lnb, bo,
                                   P16p, cp, WvTp, WoTp, b2p, csp, x, x16p);

    dim3 gv(5, NTOK/128);
    gemm_h<<<gv, 256, HSMEM>>>(x16p, WvTp, bv, nullptr, nullptr, v16p,
                               nullptr, nullptr, nullptr,
                               P16p, cp, sc, wwp, rwp, 4);

    chunk_attn_mma<<<NCHUNK, 256, CSMEM>>>(rwp, wwp, v16p, ret16p, mup, rip);

    dim3 go(4, NTOK/128);
    gemm_h<<<go, 256, HSMEM>>>(ret16p, WoTp, b2p, x, out, nullptr,
                               mup, rip, csp,
                               nullptr, nullptr, nullptr, nullptr, nullptr, 4);
}

// round 17
// speedup vs baseline: 1.0142x; 1.0142x over previous
#include <cuda_runtime.h>
#include <cuda_fp16.h>
#include <math.h>
#include <stdint.h>

// Problem constants
#define NTOK (8*8192)        // 65536 tokens
#define DIMC 512
#define NSLOT 64
#define CHUNKT 64
#define NCHUNK (NTOK/CHUNKT) // 1024

// ---------------- scratch ----------------
__device__ __half g_x16  [(size_t)NTOK*DIMC];
__device__ __half g_v16  [(size_t)NTOK*DIMC];
__device__ __half g_ret16[(size_t)NTOK*DIMC];
__device__ __half g_ww [(size_t)NTOK*NSLOT];
__device__ __half g_rw [(size_t)NTOK*NSLOT];
__device__ __half g_WvT16[DIMC*DIMC];   // half(Wv) transposed: [n][k]
__device__ __half g_WoT16[DIMC*DIMC];   // half(ln_g ⊙ Wo) transposed: [n][k]
__device__ __half g_P16T [128*DIMC];    // half([Wk@SKᵀ | Wq@SKᵀ]) transposed: [s][k]
__device__ float  g_c   [128];
__device__ float  g_b2  [DIMC];         // bo + ln_b @ Wo
__device__ float  g_cs  [DIMC];         // colsum of (ln_g ⊙ Wo)
__device__ float  g_mu  [NTOK];
__device__ float  g_ri  [NTOK];

// ---------------- helpers ----------------
__device__ __forceinline__ unsigned f2tf32(float x) {
    unsigned r;
    asm("cvt.rna.tf32.f32 %0, %1;" : "=r"(r) : "f"(x));
    return r;
}

__device__ __forceinline__ void mma_tf32(float c[4],
    unsigned a0, unsigned a1, unsigned a2, unsigned a3,
    unsigned b0, unsigned b1)
{
    asm volatile(
        "mma.sync.aligned.m16n8k8.row.col.f32.tf32.tf32.f32 "
        "{%0,%1,%2,%3},{%4,%5,%6,%7},{%8,%9},{%0,%1,%2,%3};"
        : "+f"(c[0]), "+f"(c[1]), "+f"(c[2]), "+f"(c[3])
        : "r"(a0), "r"(a1), "r"(a2), "r"(a3), "r"(b0), "r"(b1));
}

__device__ __forceinline__ void mma_f16(float c[4],
    unsigned a0, unsigned a1, unsigned a2, unsigned a3,
    unsigned b0, unsigned b1)
{
    asm volatile(
        "mma.sync.aligned.m16n8k16.row.col.f32.f16.f16.f32 "
        "{%0,%1,%2,%3},{%4,%5,%6,%7},{%8,%9},{%0,%1,%2,%3};"
        : "+f"(c[0]), "+f"(c[1]), "+f"(c[2]), "+f"(c[3])
        : "r"(a0), "r"(a1), "r"(a2), "r"(a3), "r"(b0), "r"(b1));
}

__device__ __forceinline__ void ldsm_x4(
    unsigned& r0, unsigned& r1, unsigned& r2, unsigned& r3, unsigned addr)
{
    asm volatile("ldmatrix.sync.aligned.m8n8.x4.shared.b16 {%0,%1,%2,%3}, [%4];"
        : "=r"(r0), "=r"(r1), "=r"(r2), "=r"(r3) : "r"(addr));
}

__device__ __forceinline__ void cpcg16(unsigned smem_addr, const void* g) {
    asm volatile("cp.async.cg.shared.global [%0], [%1], 16;\n"
                 :: "r"(smem_addr), "l"(g));
}
#define CP_COMMIT() asm volatile("cp.async.commit_group;\n" ::: "memory")
#define CP_WAIT0()  asm volatile("cp.async.wait_group 0;\n" ::: "memory")
#define CP_WAIT1()  asm volatile("cp.async.wait_group 1;\n" ::: "memory")
#define CP_WAIT2()  asm volatile("cp.async.wait_group 2;\n" ::: "memory")

// ======== fused prep + x->half (overlapped in one launch) ========
#define N2H 16384

__global__ __launch_bounds__(256) void prep_fused(
    const float* __restrict__ Wk, const float* __restrict__ bk,
    const float* __restrict__ Wq, const float* __restrict__ bq,
    const float* __restrict__ SK,
    const float* __restrict__ Wv, const float* __restrict__ Wo,
    const float* __restrict__ lng, const float* __restrict__ lnb,
    const float* __restrict__ bo,
    __half* __restrict__ P16T, float* __restrict__ c,
    __half* __restrict__ WvT16, __half* __restrict__ WoT16,
    float* __restrict__ b2, float* __restrict__ cs,
    const float* __restrict__ X, __half* __restrict__ X16)
{
    const int blk = blockIdx.x;
    const int s = threadIdx.x;

    if (blk >= 514) {
        size_t base = ((size_t)(blk - 514) * 256 + s) * 8;
        float4 a = *(const float4*)(X + base);
        float4 b = *(const float4*)(X + base + 4);
        __half2 h[4];
        h[0] = __floats2half2_rn(a.x, a.y);
        h[1] = __floats2half2_rn(a.z, a.w);
        h[2] = __floats2half2_rn(b.x, b.y);
        h[3] = __floats2half2_rn(b.z, b.w);
        *(uint4*)(X16 + base) = *(uint4*)h;
        return;
    }

    if (blk == 513) {
        #pragma unroll
        for (int j = 0; j < 2; j++) {
            int n = s * 2 + j;
            float a = 0.f, g = 0.f;
            for (int k = 0; k < DIMC; k++) {
                float w = Wo[(size_t)k*DIMC + n];
                a = fmaf(lnb[k], w, a);
                g = fmaf(lng[k], w, g);
            }
            b2[n] = a + bo[n];
            cs[n] = g;
        }
        return;
    }

    __shared__ float rk[DIMC];
    __shared__ float rq[DIMC];
    if (blk < DIMC) {
        for (int d = s; d < DIMC; d += 256) {
            rk[d] = Wk[(size_t)blk*DIMC + d];
            rq[d] = Wq[(size_t)blk*DIMC + d];
        }
    } else {
        for (int d = s; d < DIMC; d += 256) { rk[d] = bk[d]; rq[d] = bq[d]; }
    }
    __syncthreads();

    if (s < 128) {
        const int slot = s & 63;
        const float* row = (s < 64) ? rk : rq;
        float a = 0.f;
        const float* skr = SK + (size_t)slot*DIMC;
        #pragma unroll 8
        for (int d = 0; d < DIMC; d++) a = fmaf(row[d], skr[d], a);
        if (blk < DIMC) P16T[(size_t)s*DIMC + blk] = __float2half_rn(a);
        else            c[s] = a;
    }
    if (blk < DIMC) {
        const float gk = lng[blk];
        for (int n = s; n < DIMC; n += 256) {
            WvT16[(size_t)n*DIMC + blk] = __float2half_rn(Wv[(size_t)blk*DIMC + n]);
            WoT16[(size_t)n*DIMC + blk] = __float2half_rn(gk * Wo[(size_t)blk*DIMC + n]);
        }
    }
}

// ======== fp16 GEMM, ldmatrix, 4-stage cp.async (R15 loop, hoisted LDSM) ========
#define HROWB 80
#define HSTG 10240
#define HSMEM (8*HSTG)      // 81920
#define NIT 16

__global__ __launch_bounds__(256, 2) void gemm_h(
    const __half* __restrict__ A16, const __half* __restrict__ BT16,
    const float* __restrict__ bias, const float* __restrict__ resid,
    float* __restrict__ C, __half* __restrict__ C16,
    const float* __restrict__ rowmu, const float* __restrict__ rowri,
    const float* __restrict__ cs,
    const __half* __restrict__ P16T, const float* __restrict__ cvec,
    const float* __restrict__ scale_p,
    __half* __restrict__ ww, __half* __restrict__ rw, int nNormal)
{
    extern __shared__ __align__(16) char smraw[];
    float* L = (float*)smraw;          // logits alias [128][68]
    __shared__ float csh[128];

    const int tid  = threadIdx.x;
    const int lane = tid & 31;
    const int wid  = tid >> 5;
    const int warp_m = wid >> 2;
    const int warp_n = wid & 3;
    const int gid = lane >> 2;
    const int tig = lane & 3;
    const int m0 = blockIdx.y * 128;
    const bool is_logit = (P16T != nullptr) && ((int)blockIdx.x == nNormal);
    const int n0 = is_logit ? 0 : blockIdx.x * 128;
    const __half* Bsrc = is_logit ? P16T : BT16;

    if (is_logit && tid < 128) csh[tid] = cvec[tid];

    const unsigned sb = (unsigned)__cvta_generic_to_shared(smraw);

    const int grp = lane >> 3;
    const unsigned aRowL = (unsigned)(warp_m*64 + (grp & 1)*8 + (lane & 7));
    const unsigned aKadd = (unsigned)((grp >> 1) * 16);
    const unsigned bRowL = (unsigned)(warp_n*32 + (grp >> 1)*8 + (lane & 7));
    const unsigned bKadd = (unsigned)((grp & 1) * 16);

    float acc[4][4][4] = {};

    auto stageAB = [&](int st, int k0) {
        #pragma unroll
        for (int h = 0; h < 2; h++) {
            int cch = tid + h*256;
            int r = cch >> 2, j = cch & 3;
            unsigned off = (unsigned)(r*HROWB + j*16);
            cpcg16(sb + st*HSTG + off, A16 + (size_t)(m0 + r)*DIMC + k0 + j*8);
            cpcg16(sb + 4*HSTG + st*HSTG + off, Bsrc + (size_t)(n0 + r)*DIMC + k0 + j*8);
        }
    };

    stageAB(0, 0);   CP_COMMIT();
    stageAB(1, 32);  CP_COMMIT();
    stageAB(2, 64);  CP_COMMIT();

    for (int it = 0; it < NIT; it++) {
        if (it < NIT - 2)      { CP_WAIT2(); }
        else if (it == NIT - 2){ CP_WAIT1(); }
        else                   { CP_WAIT0(); }
        __syncthreads();
        if (it + 3 < NIT) {
            stageAB((it + 3) & 3, (it + 3) * 32);
            CP_COMMIT();
        }
        const int st = it & 3;
        const unsigned aB = sb + st*HSTG + aRowL*HROWB + aKadd;
        const unsigned bB = sb + 4*HSTG + st*HSTG + bRowL*HROWB + bKadd;

        // hoist ALL fragment loads for both ks groups (12 LDSM, MLP-overlapped)
        unsigned af[2][4][4];
        unsigned bf[2][4][2];
        #pragma unroll
        for (int ks = 0; ks < 2; ks++) {
            #pragma unroll
            for (int mt = 0; mt < 4; mt++)
                ldsm_x4(af[ks][mt][0], af[ks][mt][1], af[ks][mt][2], af[ks][mt][3],
                        aB + (unsigned)(mt*16*HROWB + ks*32));
            #pragma unroll
            for (int ntp = 0; ntp < 2; ntp++)
                ldsm_x4(bf[ks][2*ntp][0], bf[ks][2*ntp][1],
                        bf[ks][2*ntp+1][0], bf[ks][2*ntp+1][1],
                        bB + (unsigned)(ntp*16*HROWB + ks*32));
        }
        // 64-MMA uninterrupted burst (same order as before: ks, mt, nt)
        #pragma unroll
        for (int ks = 0; ks < 2; ks++)
            #pragma unroll
            for (int mt = 0; mt < 4; mt++)
                #pragma unroll
                for (int nt = 0; nt < 4; nt++)
                    mma_f16(acc[mt][nt], af[ks][mt][0], af[ks][mt][1],
                            af[ks][mt][2], af[ks][mt][3],
                            bf[ks][nt][0], bf[ks][nt][1]);
    }

    if (!is_logit) {
        #pragma unroll
        for (int nt = 0; nt < 4; nt++) {
            int cb = n0 + warp_n * 32 + nt * 8 + 2 * tig;
            float b0 = bias[cb], b1 = bias[cb + 1];
            float cs0 = 0.f, cs1 = 0.f;
            if (rowmu) { cs0 = cs[cb]; cs1 = cs[cb + 1]; }
            #pragma unroll
            for (int mt = 0; mt < 4; mt++) {
                int rA = m0 + warp_m * 64 + mt * 16 + gid;
                int rB = rA + 8;
                size_t offA = (size_t)rA * DIMC + cb;
                size_t offB = (size_t)rB * DIMC + cb;
                if (rowmu) {
                    float muA = rowmu[rA], riA = rowri[rA];
                    float muB = rowmu[rB], riB = rowri[rB];
                    float2 o0, o1;
                    o0.x = riA*acc[mt][nt][0] - riA*muA*cs0 + b0;
                    o0.y = riA*acc[mt][nt][1] - riA*muA*cs1 + b1;
                    o1.x = riB*acc[mt][nt][2] - riB*muB*cs0 + b0;
                    o1.y = riB*acc[mt][nt][3] - riB*muB*cs1 + b1;
                    float2 e0 = *(const float2*)(resid + offA);
                    float2 e1 = *(const float2*)(resid + offB);
                    o0.x += e0.x; o0.y += e0.y;
                    o1.x += e1.x; o1.y += e1.y;
                    *(float2*)(C + offA) = o0;
                    *(float2*)(C + offB) = o1;
                } else {
                    *(__half2*)(C16 + offA) =
                        __floats2half2_rn(acc[mt][nt][0] + b0, acc[mt][nt][1] + b1);
                    *(__half2*)(C16 + offB) =
                        __floats2half2_rn(acc[mt][nt][2] + b0, acc[mt][nt][3] + b1);
                }
            }
        }
    } else {
        __syncthreads();
        const float sc = scale_p[0];
        #pragma unroll
        for (int pass = 0; pass < 2; pass++) {
            if ((warp_n >> 1) == pass) {
                int halfn = warp_n & 1;
                #pragma unroll
                for (int nt = 0; nt < 4; nt++) {
                    int cl = halfn * 32 + nt * 8 + 2 * tig;
                    int cg = pass * 64 + cl;
                    float c0v = csh[cg], c1v = csh[cg + 1];
                    #pragma unroll
                    for (int mt = 0; mt < 4; mt++) {
                        int rr = warp_m * 64 + mt * 16 + gid;
                        L[ rr    *68 + cl    ] = (acc[mt][nt][0] + c0v) * sc;
                        L[ rr    *68 + cl + 1] = (acc[mt][nt][1] + c1v) * sc;
                        L[(rr+8) *68 + cl    ] = (acc[mt][nt][2] + c0v) * sc;
                        L[(rr+8) *68 + cl + 1] = (acc[mt][nt][3] + c1v) * sc;
                    }
                }
            }
            __syncthreads();
            {
                int t = tid >> 1, hh = tid & 1;
                float* Lr = L + t*68 + hh*32;
                float mx = -1e30f;
                #pragma unroll 8
                for (int s = 0; s < 32; s++) mx = fmaxf(mx, Lr[s]);
                mx = fmaxf(mx, __shfl_xor_sync(0xffffffffu, mx, 1));
                float sum = 0.f;
                #pragma unroll 8
                for (int s = 0; s < 32; s++) { float e = expf(Lr[s]-mx); Lr[s] = e; sum += e; }
                sum += __shfl_xor_sync(0xffffffffu, sum, 1);
                float rv = 1.f / sum;
                __half* op = (pass ? rw : ww) + (size_t)(m0 + t) * NSLOT + hh*32;
                #pragma unroll
                for (int s = 0; s < 32; s += 4) {
                    __half2 p0 = __floats2half2_rn(Lr[s]*rv,   Lr[s+1]*rv);
                    __half2 p1 = __floats2half2_rn(Lr[s+2]*rv, Lr[s+3]*rv);
                    uint2 u;
                    u.x = *(unsigned*)&p0;
                    u.y = *(unsigned*)&p1;
                    *(uint2*)(op + s) = u;
                }
            }
            __syncthreads();
        }
    }
}

// ======== per-chunk tf32 MMA + fused LN stats + reg-staged V prefetch ========
#define CSMEM (64*68*4*2 + 64*132*4)   // 68608

__global__ __launch_bounds__(256) void chunk_attn_mma(
    const __half* __restrict__ rwh, const __half* __restrict__ wwh,
    const __half* __restrict__ v16, __half* __restrict__ ret16,
    float* __restrict__ mu, float* __restrict__ ri)
{
    extern __shared__ __align__(16) char cbuf[];
    unsigned* RW = (unsigned*)cbuf;
    unsigned* WT = RW + 64*68;
    unsigned* VS = WT + 64*68;
    float*    red = (float*)VS;        // 512 floats, used after last slice
    const int tid  = threadIdx.x;
    const int lane = tid & 31;
    const int wid  = tid >> 5;
    const int gid = lane >> 2;
    const int tig = lane & 3;
    const int chunk0 = blockIdx.x * CHUNKT;

    int vr[4], vc[4];
    #pragma unroll
    for (int k = 0; k < 4; k++) {
        int idx = tid + k*256;
        vr[k] = idx >> 4;
        vc[k] = (idx & 15) << 3;
    }

    uint4 pv[4];
    #pragma unroll
    for (int k = 0; k < 4; k++)
        pv[k] = *(const uint4*)(v16 + (size_t)(chunk0+vr[k])*DIMC + vc[k]);

    #pragma unroll
    for (int k = 0; k < 4; k++) {
        int idx = tid + k*256;
        int r = idx >> 4, c4 = (idx & 15) << 2;
        uint2 ha = *(const uint2*)(rwh + (size_t)(chunk0+r)*NSLOT + c4);
        float2 a0 = __half22float2(*(__half2*)&ha.x);
        float2 a1 = __half22float2(*(__half2*)&ha.y);
        float4 va; va.x = a0.x; va.y = a0.y; va.z = a1.x; va.w = a1.y;
        *(float4*)(RW + r*68 + c4) = va;
        uint2 hb = *(const uint2*)(wwh + (size_t)(chunk0+r)*NSLOT + c4);
        float2 b0 = __half22float2(*(__half2*)&hb.x);
        float2 b1 = __half22float2(*(__half2*)&hb.y);
        WT[(c4    )*68 + r] = __float_as_uint(b0.x);
        WT[(c4 + 1)*68 + r] = __float_as_uint(b0.y);
        WT[(c4 + 2)*68 + r] = __float_as_uint(b1.x);
        WT[(c4 + 3)*68 + r] = __float_as_uint(b1.y);
    }
    __syncthreads();

    const int wm = wid >> 2;
    const int wn = wid & 3;
    float a1acc[2][2][4] = {};
    #pragma unroll
    for (int kk = 0; kk < 64; kk += 8) {
        unsigned af[2][4];
        #pragma unroll
        for (int mt = 0; mt < 2; mt++) {
            int r = wm*32 + mt*16 + gid;
            af[mt][0] = RW[ r     *68 + kk + tig    ];
            af[mt][1] = RW[(r + 8)*68 + kk + tig    ];
            af[mt][2] = RW[ r     *68 + kk + tig + 4];
            af[mt][3] = RW[(r + 8)*68 + kk + tig + 4];
        }
        unsigned bf[2][2];
        #pragma unroll
        for (int nt = 0; nt < 2; nt++) {
            int cc = wn*16 + nt*8 + gid;
            bf[nt][0] = WT[(kk + tig    )*68 + cc];
            bf[nt][1] = WT[(kk + tig + 4)*68 + cc];
        }
        #pragma unroll
        for (int mt = 0; mt < 2; mt++)
            #pragma unroll
            for (int nt = 0; nt < 2; nt++)
                mma_tf32(a1acc[mt][nt], af[mt][0], af[mt][1], af[mt][2], af[mt][3],
                         bf[nt][0], bf[nt][1]);
    }
    __syncthreads();

    #pragma unroll
    for (int mt = 0; mt < 2; mt++) {
        int r0 = wm*32 + mt*16 + gid;
        #pragma unroll
        for (int nt = 0; nt < 2; nt++) {
            int cc = wn*16 + nt*8 + 2*tig;
            RW[ r0    *68 + cc    ] = f2tf32((cc     <= r0    ) ? a1acc[mt][nt][0] : 0.f);
            RW[ r0    *68 + cc + 1] = f2tf32((cc + 1 <= r0    ) ? a1acc[mt][nt][1] : 0.f);
            RW[(r0+8) *68 + cc    ] = f2tf32((cc     <= r0 + 8) ? a1acc[mt][nt][2] : 0.f);
            RW[(r0+8) *68 + cc + 1] = f2tf32((cc + 1 <= r0 + 8) ? a1acc[mt][nt][3] : 0.f);
        }
    }
    __syncthreads();

    float s_acc[2][2] = {}, ss_acc[2][2] = {};

    for (int d0 = 0; d0 < DIMC; d0 += 128) {
        #pragma unroll
        for (int k = 0; k < 4; k++) {
            float2 f0 = __half22float2(*(__half2*)&pv[k].x);
            float2 f1 = __half22float2(*(__half2*)&pv[k].y);
            float2 f2 = __half22float2(*(__half2*)&pv[k].z);
            float2 f3 = __half22float2(*(__half2*)&pv[k].w);
            float4 o0; o0.x = f0.x; o0.y = f0.y; o0.z = f1.x; o0.w = f1.y;
            float4 o1; o1.x = f2.x; o1.y = f2.y; o1.z = f3.x; o1.w = f3.y;
            *(float4*)(VS + vr[k]*132 + vc[k])     = o0;
            *(float4*)(VS + vr[k]*132 + vc[k] + 4) = o1;
        }
        __syncthreads();

        if (d0 + 128 < DIMC) {
            #pragma unroll
            for (int k = 0; k < 4; k++)
                pv[k] = *(const uint4*)(v16 + (size_t)(chunk0+vr[k])*DIMC
                                        + d0 + 128 + vc[k]);
        }

        float a2[2][4][4] = {};
        #pragma unroll
        for (int ks = 0; ks < 8; ks++) {
            unsigned af[2][4];
            #pragma unroll
            for (int mt = 0; mt < 2; mt++) {
                int r = wm*32 + mt*16 + gid;
                af[mt][0] = RW[ r     *68 + ks*8 + tig    ];
                af[mt][1] = RW[(r + 8)*68 + ks*8 + tig    ];
                af[mt][2] = RW[ r     *68 + ks*8 + tig + 4];
                af[mt][3] = RW[(r + 8)*68 + ks*8 + tig + 4];
            }
            unsigned bf[4][2];
            #pragma unroll
            for (int nt = 0; nt < 4; nt++) {
                int cc = wn*32 + nt*8 + gid;
                bf[nt][0] = VS[(ks*8 + tig    )*132 + cc];
                bf[nt][1] = VS[(ks*8 + tig + 4)*132 + cc];
            }
            #pragma unroll
            for (int mt = 0; mt < 2; mt++)
                #pragma unroll
                for (int nt = 0; nt < 4; nt++)
                    mma_tf32(a2[mt][nt], af[mt][0], af[mt][1],
                             af[mt][2], af[mt][3], bf[nt][0], bf[nt][1]);
        }

        #pragma unroll
        for (int mt = 0; mt < 2; mt++) {
            int r0 = wm*32 + mt*16 + gid;
            #pragma unroll
            for (int nt = 0; nt < 4; nt++) {
                int cc = wn*32 + nt*8 + 2*tig;
                __half2 h0 = __floats2half2_rn(a2[mt][nt][0], a2[mt][nt][1]);
                __half2 h1 = __floats2half2_rn(a2[mt][nt][2], a2[mt][nt][3]);
                *(__half2*)(ret16 + (size_t)(chunk0 + r0    )*DIMC + d0 + cc) = h0;
                *(__half2*)(ret16 + (size_t)(chunk0 + r0 + 8)*DIMC + d0 + cc) = h1;
                float2 f0 = __half22float2(h0);
                float2 f1 = __half22float2(h1);
                s_acc[mt][0]  += f0.x + f0.y;
                ss_acc[mt][0] += fmaf(f0.x, f0.x, f0.y*f0.y);
                s_acc[mt][1]  += f1.x + f1.y;
                ss_acc[mt][1] += fmaf(f1.x, f1.x, f1.y*f1.y);
            }
        }
        __syncthreads();
    }

    #pragma unroll
    for (int mt = 0; mt < 2; mt++)
        #pragma unroll
        for (int hf = 0; hf < 2; hf++) {
            float s = s_acc[mt][hf], ss = ss_acc[mt][hf];
            s  += __shfl_xor_sync(0xffffffffu, s, 1);
            s  += __shfl_xor_sync(0xffffffffu, s, 2);
            ss += __shfl_xor_sync(0xffffffffu, ss, 1);
            ss += __shfl_xor_sync(0xffffffffu, ss, 2);
            if (tig == 0) {
                int row = wm*32 + mt*16 + hf*8 + gid;
                red[wn*64 + row]       = s;
                red[256 + wn*64 + row] = ss;
            }
        }
    __syncthreads();
    if (tid < 64) {
        float s  = red[tid] + red[64+tid] + red[128+tid] + red[192+tid];
        float ss = red[256+tid] + red[320+tid] + red[384+tid] + red[448+tid];
        float m = s * (1.f/512.f);
        mu[chunk0 + tid] = m;
        ri[chunk0 + tid] = rsqrtf(ss * (1.f/512.f) - m*m + 1e-5f);
    }
}

// ---------------- launch ----------------
extern "C" void kernel_launch(void* const* d_in, const int* in_sizes, int n_in,
                              void* d_out, int out_size)
{
    (void)in_sizes; (void)n_in; (void)out_size;
    const float* x   = (const float*)d_in[0];
    const float* sk  = (const float*)d_in[1];
    const float* Wk  = (const float*)d_in[2];
    const float* bk  = (const float*)d_in[3];
    const float* Wq  = (const float*)d_in[4];
    const float* bq  = (const float*)d_in[5];
    const float* Wv  = (const float*)d_in[6];
    const float* bv  = (const float*)d_in[7];
    const float* sc  = (const float*)d_in[8];
    const float* lng = (const float*)d_in[9];
    const float* lnb = (const float*)d_in[10];
    const float* Wo  = (const float*)d_in[11];
    const float* bo  = (const float*)d_in[12];
    float* out = (float*)d_out;

    float *cp,*b2p,*csp,*mup,*rip;
    __half *x16p,*v16p,*ret16p,*WvTp,*WoTp,*P16p,*wwp,*rwp;
    cudaGetSymbolAddress((void**)&x16p,  g_x16);
    cudaGetSymbolAddress((void**)&v16p,  g_v16);
    cudaGetSymbolAddress((void**)&ret16p,g_ret16);
    cudaGetSymbolAddress((void**)&wwp,   g_ww);
    cudaGetSymbolAddress((void**)&rwp,   g_rw);
    cudaGetSymbolAddress((void**)&cp,    g_c);
    cudaGetSymbolAddress((void**)&b2p,   g_b2);
    cudaGetSymbolAddress((void**)&csp,   g_cs);
    cudaGetSymbolAddress((void**)&mup,   g_mu);
    cudaGetSymbolAddress((void**)&rip,   g_ri);
    cudaGetSymbolAddress((void**)&WvTp,  g_WvT16);
    cudaGetSymbolAddress((void**)&WoTp,  g_WoT16);
    cudaGetSymbolAddress((void**)&P16p,  g_P16T);

    cudaFuncSetAttribute(gemm_h, cudaFuncAttributeMaxDynamicSharedMemorySize, HSMEM);
    cudaFuncSetAttribute(chunk_attn_mma, cudaFuncAttributeMaxDynamicSharedMemorySize, CSMEM);

    prep_fused<<<514 + N2H, 256>>>(Wk, bk, Wq, bq, sk, Wv, Wo, lng, lnb, bo,
                                   P16p, cp, WvTp, WoTp, b2p, csp, x, x16p);

    dim3 gv(5, NTOK/128);
    gemm_h<<<gv, 256, HSMEM>>>(x16p, WvTp, bv, nullptr, nullptr, v16p,
                               nullptr, nullptr, nullptr,
                               P16p, cp, sc, wwp, rwp, 4);

    chunk_attn_mma<<<NCHUNK, 256, CSMEM>>>(rwp, wwp, v16p, ret16p, mup, rip);

    dim3 go(4, NTOK/128);
    gemm_h<<<go, 256, HSMEM>>>(ret16p, WoTp, b2p, x, out, nullptr,
                               mup, rip, csp,
                               nullptr, nullptr, nullptr, nullptr, nullptr, 4);
}